// round 7
// baseline (speedup 1.0000x reference)
#include <cuda_runtime.h>
#include <cstdint>

// ---------------------------------------------------------------------------
// TransferSH R7: cp.async (LDGSTS) smem-staged gather.
//
// Evidence chain:
//   R4/R6: loads+consume inside divergent offset switch -> ~4 serial DRAM
//          exposures/point, DRAM capped ~65%.
//   R5:    register-batched loads -> 1 exposure but 48 live dest regs,
//          occ 32%, DRAM 49%.
// cp.async breaks the tradeoff: 12x16B global->shared copies per thread with
// NO destination registers, no divergence, single wait; consumption reads the
// row at dynamic offset (id&3) from smem (affine addressing, immediate-offset
// LDS). DRAM becomes the only binding resource.
//
// Output layout (float32): [ clipped colors (N*3) , mean_abs scalar (1) ]
// ---------------------------------------------------------------------------

__device__ float g_affine[12];   // row-major 3x4, eye added

#define SH_C0 0.28209479177387814f
#define SH_C1 0.4886025119029199f
#define SH_C2_0 1.0925484305920792f
#define SH_C2_1 (-1.0925484305920792f)
#define SH_C2_2 0.31539156525252005f
#define SH_C2_3 (-1.0925484305920792f)
#define SH_C2_4 0.5462742152960396f
#define SH_C3_0 (-0.5900435899266435f)
#define SH_C3_1 2.890611442640554f
#define SH_C3_2 (-0.4570457994644658f)
#define SH_C3_3 0.3731763325901154f
#define SH_C3_4 (-0.4570457994644658f)
#define SH_C3_5 1.445305721320277f
#define SH_C3_6 (-0.5900435899266435f)

// ---------------------------------------------------------------------------
// Kernel A: 1x16 -> 32 (LN, relu) -> 12 MLP, affine build, mean|.|
// ---------------------------------------------------------------------------
__global__ void affine_kernel(const float* __restrict__ glo,
                              const float* __restrict__ w1,
                              const float* __restrict__ b1,
                              const float* __restrict__ ln_w,
                              const float* __restrict__ ln_b,
                              const float* __restrict__ w2,
                              const float* __restrict__ b2,
                              float* __restrict__ out_scalar)
{
    if (threadIdx.x != 0 || blockIdx.x != 0) return;

    float g[16];
#pragma unroll
    for (int k = 0; k < 16; k++) g[k] = glo[k];

    float h[32];
    float mu = 0.f;
#pragma unroll
    for (int j = 0; j < 32; j++) {
        float acc = b1[j];
#pragma unroll
        for (int k = 0; k < 16; k++) acc += g[k] * w1[k * 32 + j];
        h[j] = acc;
        mu += acc;
    }
    mu *= (1.f / 32.f);
    float var = 0.f;
#pragma unroll
    for (int j = 0; j < 32; j++) {
        float d = h[j] - mu;
        var += d * d;
    }
    var *= (1.f / 32.f);
    float inv = rsqrtf(var + 1e-5f);
#pragma unroll
    for (int j = 0; j < 32; j++) {
        float v = (h[j] - mu) * inv * ln_w[j] + ln_b[j];
        h[j] = v > 0.f ? v : 0.f;
    }

    float s = 0.f;
#pragma unroll
    for (int c = 0; c < 12; c++) {
        float o = b2[c];
#pragma unroll
        for (int j = 0; j < 32; j++) o += h[j] * w2[j * 12 + c];
        o *= 1e-12f;
        s += fabsf(o);
        g_affine[c] = o;
    }
    g_affine[0]  += 1.f;
    g_affine[5]  += 1.f;
    g_affine[10] += 1.f;

    *out_scalar = s * (1.f / 12.f);
}

// ---------------------------------------------------------------------------
// Kernel B: per-point SH evaluation + cp.async staged gather + affine + clamp
// ---------------------------------------------------------------------------
#define TSH_THREADS 128
#define STAGE_STRIDE 52   // floats per thread: 208 B (13 x 16 B, cp.async-aligned;
                          // bank stride 20 mod 32 -> ~2-way LDS conflicts)

__global__ void __launch_bounds__(TSH_THREADS)
transfer_sh_kernel(const float* __restrict__ positions,   // (N,3)
                   const int*   __restrict__ indexes,     // (N,)
                   const float* __restrict__ cam_pos,     // (3,)
                   const float* __restrict__ base_sh,     // (NP,3,1)
                   const float* __restrict__ higher_sh,   // (NP,3,15)
                   float*       __restrict__ out,         // (N,3)
                   int n)
{
    __shared__ float stage[TSH_THREADS * STAGE_STRIDE];

    int t = threadIdx.x;
    int i = blockIdx.x * TSH_THREADS + t;
    if (i >= n) return;

    // ---- index load, then 12 cp.async 16B chunks: no dest regs, MLP=12 ----
    int id = __ldg(indexes + i);
    unsigned fstart = (unsigned)id * 45u;                 // < 2^31

    const char* gsrc = (const char*)higher_sh + (size_t)(fstart >> 2) * 16;
    uint32_t sdst = (uint32_t)__cvta_generic_to_shared(&stage[t * STAGE_STRIDE]);

#pragma unroll
    for (int j = 0; j < 12; j++) {
        asm volatile("cp.async.cg.shared.global [%0], [%1], 16;\n"
                     :: "r"(sdst + j * 16), "l"(gsrc + j * 16) : "memory");
    }
    asm volatile("cp.async.commit_group;\n" ::: "memory");

    // ---- base_sh gather (scalar, 12B row) ----
    const float* brow = base_sh + (unsigned)id * 3u;
    float b0  = __ldg(brow + 0);
    float b1v = __ldg(brow + 1);
    float b2v = __ldg(brow + 2);

    // ---- direction + SH basis (overlaps with staged gathers in flight) ----
    float dx = __ldg(positions + 3 * i + 0) - __ldg(cam_pos + 0);
    float dy = __ldg(positions + 3 * i + 1) - __ldg(cam_pos + 1);
    float dz = __ldg(positions + 3 * i + 2) - __ldg(cam_pos + 2);
    float rinv = rsqrtf(dx * dx + dy * dy + dz * dz);
    float x = dx * rinv, y = dy * rinv, z = dz * rinv;

    float xx = x * x, yy = y * y, zz = z * z;
    float xy = x * y, yz = y * z, xz = x * z;

    // basis[1..15] of the reference (DC term folded into col init)
    float basis[15];
    basis[0]  = -SH_C1 * y;
    basis[1]  =  SH_C1 * z;
    basis[2]  = -SH_C1 * x;
    basis[3]  = SH_C2_0 * xy;
    basis[4]  = SH_C2_1 * yz;
    basis[5]  = SH_C2_2 * (2.f * zz - xx - yy);
    basis[6]  = SH_C2_3 * xz;
    basis[7]  = SH_C2_4 * (xx - yy);
    basis[8]  = SH_C3_0 * y * (3.f * xx - yy);
    basis[9]  = SH_C3_1 * xy * z;
    basis[10] = SH_C3_2 * y * (4.f * zz - xx - yy);
    basis[11] = SH_C3_3 * z * (2.f * zz - 3.f * xx - 3.f * yy);
    basis[12] = SH_C3_4 * x * (4.f * zz - xx - yy);
    basis[13] = SH_C3_5 * z * (xx - yy);
    basis[14] = SH_C3_6 * x * (xx - yy);

    float col[3];
    col[0] = b0  * SH_C0 + 0.5f;
    col[1] = b1v * SH_C0 + 0.5f;
    col[2] = b2v * SH_C0 + 0.5f;

    // ---- wait for this thread's staged chunks (per-thread semantics) ----
    asm volatile("cp.async.wait_group 0;\n" ::: "memory");

    // Row starts at float (id&3) inside this thread's 48-float window.
    // Affine base + compile-time offsets -> 45 immediate-offset LDS.
    const float* row = &stage[t * STAGE_STRIDE] + (fstart & 3u);
#pragma unroll
    for (int c = 0; c < 3; c++) {
        float acc = 0.f;
#pragma unroll
        for (int k = 0; k < 15; k++)
            acc += row[c * 15 + k] * basis[k];
        col[c] += acc;
    }

    // ---- affine + clamp + store ----
#pragma unroll
    for (int r = 0; r < 3; r++) {
        float o = g_affine[r * 4 + 0] * col[0]
                + g_affine[r * 4 + 1] * col[1]
                + g_affine[r * 4 + 2] * col[2]
                + g_affine[r * 4 + 3];
        o = fminf(fmaxf(o, 0.f), 1.f);
        out[3 * i + r] = o;
    }
}

// ---------------------------------------------------------------------------
// kernel_launch
// input order: positions, indexes, cam_pos, glo_feature, base_sh, higher_sh,
//              w1, b1, ln_w, ln_b, w2, b2
// ---------------------------------------------------------------------------
extern "C" void kernel_launch(void* const* d_in, const int* in_sizes, int n_in,
                              void* d_out, int out_size)
{
    const float* positions = (const float*)d_in[0];
    const int*   indexes   = (const int*)  d_in[1];
    const float* cam_pos   = (const float*)d_in[2];
    const float* glo       = (const float*)d_in[3];
    const float* base_sh   = (const float*)d_in[4];
    const float* higher_sh = (const float*)d_in[5];
    const float* w1        = (const float*)d_in[6];
    const float* b1        = (const float*)d_in[7];
    const float* ln_w      = (const float*)d_in[8];
    const float* ln_b      = (const float*)d_in[9];
    const float* w2        = (const float*)d_in[10];
    const float* b2        = (const float*)d_in[11];

    float* out = (float*)d_out;
    int n = in_sizes[0] / 3;   // positions is (N,3)

    float* out_scalar = out + (out_size - 1);

    affine_kernel<<<1, 32>>>(glo, w1, b1, ln_w, ln_b, w2, b2, out_scalar);

    int blocks = (n + TSH_THREADS - 1) / TSH_THREADS;
    transfer_sh_kernel<<<blocks, TSH_THREADS>>>(positions, indexes, cam_pos,
                                                base_sh, higher_sh, out, n);
}

// round 8
// speedup vs baseline: 1.3432x; 1.3432x over previous
#include <cuda_runtime.h>
#include <cstdint>

// ---------------------------------------------------------------------------
// TransferSH R8: warp-cooperative coalesced gather + de-rotated smem staging.
//
// Diagnosis: per-lane gather = 12 LDG.128/lane, each instruction touching 32
// distinct 128B lines -> ~500+ L1tex wavefronts per warp-point; measured time
// matches a ~1 wf/cyc/SM wall (R4/R6 both ~134us, DRAM stuck 63-65%).
// Fix: lanes cooperate so consecutive 16B chunks of the SAME row share one
// instruction (coalesce into one wavefront per line):
//   phase A: 4 rows x chunks 0-7 per instruction (128B/row contiguous)
//   phase B: 8 rows x chunks 8-11 per instruction (64B/row)
//   base_sh: 16 rows x 16B window per instruction
// Chunks are de-rotated by (45*id mod 4) at store time into smem rows of
// stride 49 floats -> consumer rows start at float 0, compile-time LDS
// offsets, 17*lane mod 32 bank permutation = conflict-free.
//
// Output layout (float32): [ clipped colors (N*3) , mean_abs scalar (1) ]
// ---------------------------------------------------------------------------

__device__ float g_affine[12];   // row-major 3x4, eye added

#define SH_C0 0.28209479177387814f
#define SH_C1 0.4886025119029199f
#define SH_C2_0 1.0925484305920792f
#define SH_C2_1 (-1.0925484305920792f)
#define SH_C2_2 0.31539156525252005f
#define SH_C2_3 (-1.0925484305920792f)
#define SH_C2_4 0.5462742152960396f
#define SH_C3_0 (-0.5900435899266435f)
#define SH_C3_1 2.890611442640554f
#define SH_C3_2 (-0.4570457994644658f)
#define SH_C3_3 0.3731763325901154f
#define SH_C3_4 (-0.4570457994644658f)
#define SH_C3_5 1.445305721320277f
#define SH_C3_6 (-0.5900435899266435f)

// ---------------------------------------------------------------------------
// Kernel A: 1x16 -> 32 (LN, relu) -> 12 MLP, affine build, mean|.|
// ---------------------------------------------------------------------------
__global__ void affine_kernel(const float* __restrict__ glo,
                              const float* __restrict__ w1,
                              const float* __restrict__ b1,
                              const float* __restrict__ ln_w,
                              const float* __restrict__ ln_b,
                              const float* __restrict__ w2,
                              const float* __restrict__ b2,
                              float* __restrict__ out_scalar)
{
    if (threadIdx.x != 0 || blockIdx.x != 0) return;

    float g[16];
#pragma unroll
    for (int k = 0; k < 16; k++) g[k] = glo[k];

    float h[32];
    float mu = 0.f;
#pragma unroll
    for (int j = 0; j < 32; j++) {
        float acc = b1[j];
#pragma unroll
        for (int k = 0; k < 16; k++) acc += g[k] * w1[k * 32 + j];
        h[j] = acc;
        mu += acc;
    }
    mu *= (1.f / 32.f);
    float var = 0.f;
#pragma unroll
    for (int j = 0; j < 32; j++) {
        float d = h[j] - mu;
        var += d * d;
    }
    var *= (1.f / 32.f);
    float inv = rsqrtf(var + 1e-5f);
#pragma unroll
    for (int j = 0; j < 32; j++) {
        float v = (h[j] - mu) * inv * ln_w[j] + ln_b[j];
        h[j] = v > 0.f ? v : 0.f;
    }

    float s = 0.f;
#pragma unroll
    for (int c = 0; c < 12; c++) {
        float o = b2[c];
#pragma unroll
        for (int j = 0; j < 32; j++) o += h[j] * w2[j * 12 + c];
        o *= 1e-12f;
        s += fabsf(o);
        g_affine[c] = o;
    }
    g_affine[0]  += 1.f;
    g_affine[5]  += 1.f;
    g_affine[10] += 1.f;

    *out_scalar = s * (1.f / 12.f);
}

// ---------------------------------------------------------------------------
// Kernel B
// ---------------------------------------------------------------------------
#define TSH_THREADS 128
#define ROW_STRIDE  49          // floats per staged row (45 hi + 3 base + pad)

__global__ void __launch_bounds__(TSH_THREADS, 8)
transfer_sh_kernel(const float* __restrict__ positions,   // (N,3)
                   const int*   __restrict__ indexes,     // (N,)
                   const float* __restrict__ cam_pos,     // (3,)
                   const float* __restrict__ base_sh,     // (NP,3,1)
                   const float* __restrict__ higher_sh,   // (NP,3,15)
                   float*       __restrict__ out,         // (N,3)
                   int n)
{
    __shared__ float s_row[TSH_THREADS * ROW_STRIDE];

    const int t    = threadIdx.x;
    const int lane = t & 31;
    const int warp = t >> 5;
    const int i    = blockIdx.x * TSH_THREADS + t;
    const int ic   = i < n ? i : (n - 1);      // clamp so coop lanes stay valid

    float* wrow = s_row + warp * 32 * ROW_STRIDE;

    const int my_id = __ldg(indexes + ic);

    // ======== Phase A: chunks 0..7 of all 32 rows (4 rows / instruction) ====
    {
        const int rsub = lane >> 3;            // 0..3
        const int c    = lane & 7;             // chunk 0..7
        float4 v[8];
        int    e0[8];                          // de-rotated float pos of v.x
#pragma unroll
        for (int g = 0; g < 8; g++) {
            int r   = g * 4 + rsub;
            int rid = __shfl_sync(0xffffffffu, my_id, r);
            unsigned fs = (unsigned)rid * 45u;
            const float4* q = (const float4*)higher_sh + (fs >> 2) + c;
            v[g]  = __ldg(q);
            e0[g] = c * 4 - (int)(fs & 3u);    // in [-3, 28]
        }
#pragma unroll
        for (int g = 0; g < 8; g++) {
            int r = g * 4 + rsub;
            float* dst = wrow + r * ROW_STRIDE + e0[g];
            if (e0[g]     >= 0) dst[0] = v[g].x;   // upper bound <= 31 always
            if (e0[g] + 1 >= 0) dst[1] = v[g].y;
            if (e0[g] + 2 >= 0) dst[2] = v[g].z;
            if (e0[g] + 3 >= 0) dst[3] = v[g].w;
        }
    }

    // ======== Phase B: chunks 8..11 of all 32 rows (8 rows / instruction) ===
    {
        const int rsub = lane >> 2;            // 0..7
        const int c    = 8 + (lane & 3);       // chunk 8..11
        float4 v[4];
        int    e0[4];
#pragma unroll
        for (int g = 0; g < 4; g++) {
            int r   = g * 8 + rsub;
            int rid = __shfl_sync(0xffffffffu, my_id, r);
            unsigned fs = (unsigned)rid * 45u;
            const float4* q = (const float4*)higher_sh + (fs >> 2) + c;
            v[g]  = __ldg(q);
            e0[g] = c * 4 - (int)(fs & 3u);    // in [29, 44]
        }
#pragma unroll
        for (int g = 0; g < 4; g++) {
            int r = g * 8 + rsub;
            float* dst = wrow + r * ROW_STRIDE + e0[g];
            if (e0[g]     <= 44) dst[0] = v[g].x;  // lower bound >= 29 always
            if (e0[g] + 1 <= 44) dst[1] = v[g].y;
            if (e0[g] + 2 <= 44) dst[2] = v[g].z;
            if (e0[g] + 3 <= 44) dst[3] = v[g].w;
        }
    }

    // ======== base_sh: 3 floats -> staged at row floats 45..47 ==============
    {
        const int rsub = lane >> 1;            // 0..15
        const int m    = lane & 1;             // which float2 of the window
        float2 v[2];
        int    e0[2];
#pragma unroll
        for (int g = 0; g < 2; g++) {
            int r   = g * 16 + rsub;
            int rid = __shfl_sync(0xffffffffu, my_id, r);
            unsigned fs3 = (unsigned)rid * 3u;
            const float2* q2 = (const float2*)base_sh + (fs3 >> 1) + m;
            v[g]  = __ldg(q2);
            e0[g] = m * 2 - (int)(fs3 & 1u);   // in [-1, 2]
        }
#pragma unroll
        for (int g = 0; g < 2; g++) {
            int r = g * 16 + rsub;
            float* dst = wrow + r * ROW_STRIDE + 45 + e0[g];
            if (e0[g]     >= 0 && e0[g]     <= 2) dst[0] = v[g].x;
            if (e0[g] + 1 >= 0 && e0[g] + 1 <= 2) dst[1] = v[g].y;
        }
    }

    __syncwarp();

    // ======== per-thread consume: dir, basis, dot, affine, clamp ===========
    float dx = __ldg(positions + 3 * ic + 0) - __ldg(cam_pos + 0);
    float dy = __ldg(positions + 3 * ic + 1) - __ldg(cam_pos + 1);
    float dz = __ldg(positions + 3 * ic + 2) - __ldg(cam_pos + 2);
    float rinv = rsqrtf(dx * dx + dy * dy + dz * dz);
    float x = dx * rinv, y = dy * rinv, z = dz * rinv;

    float xx = x * x, yy = y * y, zz = z * z;
    float xy = x * y, yz = y * z, xz = x * z;

    float basis[15];
    basis[0]  = -SH_C1 * y;
    basis[1]  =  SH_C1 * z;
    basis[2]  = -SH_C1 * x;
    basis[3]  = SH_C2_0 * xy;
    basis[4]  = SH_C2_1 * yz;
    basis[5]  = SH_C2_2 * (2.f * zz - xx - yy);
    basis[6]  = SH_C2_3 * xz;
    basis[7]  = SH_C2_4 * (xx - yy);
    basis[8]  = SH_C3_0 * y * (3.f * xx - yy);
    basis[9]  = SH_C3_1 * xy * z;
    basis[10] = SH_C3_2 * y * (4.f * zz - xx - yy);
    basis[11] = SH_C3_3 * z * (2.f * zz - 3.f * xx - 3.f * yy);
    basis[12] = SH_C3_4 * x * (4.f * zz - xx - yy);
    basis[13] = SH_C3_5 * z * (xx - yy);
    basis[14] = SH_C3_6 * x * (xx - yy);

    const float* row = wrow + lane * ROW_STRIDE;   // de-rotated: starts at 0

    float col[3];
#pragma unroll
    for (int c = 0; c < 3; c++) {
        float acc = row[45 + c] * SH_C0 + 0.5f;
#pragma unroll
        for (int k = 0; k < 15; k++)
            acc += row[c * 15 + k] * basis[k];
        col[c] = acc;
    }

    if (i < n) {
#pragma unroll
        for (int r = 0; r < 3; r++) {
            float o = g_affine[r * 4 + 0] * col[0]
                    + g_affine[r * 4 + 1] * col[1]
                    + g_affine[r * 4 + 2] * col[2]
                    + g_affine[r * 4 + 3];
            o = fminf(fmaxf(o, 0.f), 1.f);
            out[3 * i + r] = o;
        }
    }
}

// ---------------------------------------------------------------------------
// kernel_launch
// input order: positions, indexes, cam_pos, glo_feature, base_sh, higher_sh,
//              w1, b1, ln_w, ln_b, w2, b2
// ---------------------------------------------------------------------------
extern "C" void kernel_launch(void* const* d_in, const int* in_sizes, int n_in,
                              void* d_out, int out_size)
{
    const float* positions = (const float*)d_in[0];
    const int*   indexes   = (const int*)  d_in[1];
    const float* cam_pos   = (const float*)d_in[2];
    const float* glo       = (const float*)d_in[3];
    const float* base_sh   = (const float*)d_in[4];
    const float* higher_sh = (const float*)d_in[5];
    const float* w1        = (const float*)d_in[6];
    const float* b1        = (const float*)d_in[7];
    const float* ln_w      = (const float*)d_in[8];
    const float* ln_b      = (const float*)d_in[9];
    const float* w2        = (const float*)d_in[10];
    const float* b2        = (const float*)d_in[11];

    float* out = (float*)d_out;
    int n = in_sizes[0] / 3;   // positions is (N,3)

    float* out_scalar = out + (out_size - 1);

    affine_kernel<<<1, 32>>>(glo, w1, b1, ln_w, ln_b, w2, b2, out_scalar);

    int blocks = (n + TSH_THREADS - 1) / TSH_THREADS;
    transfer_sh_kernel<<<blocks, TSH_THREADS>>>(positions, indexes, cam_pos,
                                                base_sh, higher_sh, out, n);
}